// round 4
// baseline (speedup 1.0000x reference)
#include <cuda_runtime.h>
#include <cstdint>

#define T_STEPS 1024
#define F_IN    64
#define HDIM    40
#define G4      160   // 4*H
#define R       4     // batch rows per block
#define NT      640   // threads per block (20 warps)

typedef unsigned long long ull;

// ---------------------------------------------------------------------------
// Packed f32x2 helpers (Blackwell packed fp32 FMA)
// ---------------------------------------------------------------------------
__device__ __forceinline__ ull pack2(float a, float b) {
    ull r; asm("mov.b64 %0, {%1,%2};" : "=l"(r) : "f"(a), "f"(b)); return r;
}
__device__ __forceinline__ void unpack2(ull v, float& a, float& b) {
    asm("mov.b64 {%0,%1}, %2;" : "=f"(a), "=f"(b) : "l"(v));
}
__device__ __forceinline__ void ffma2(ull& d, ull a, ull b) {
    asm("fma.rn.f32x2 %0, %1, %2, %0;" : "+l"(d) : "l"(a), "l"(b));
}

// ---------------------------------------------------------------------------
// Fast activations via MUFU (ex2 + rcp). Max error ~1e-6.
// ---------------------------------------------------------------------------
__device__ __forceinline__ float sigmoid_f(float x) {
    float e, r;
    asm("ex2.approx.f32 %0, %1;" : "=f"(e) : "f"(-1.4426950408889634f * x));
    asm("rcp.approx.f32 %0, %1;" : "=f"(r) : "f"(1.0f + e));
    return r;
}
__device__ __forceinline__ float tanh_f(float x) {
    float e, r;
    asm("ex2.approx.f32 %0, %1;" : "=f"(e) : "f"(2.8853900817779268f * x));
    asm("rcp.approx.f32 %0, %1;" : "=f"(r) : "f"(1.0f + e));
    return 1.0f - 2.0f * r;
}

__device__ __forceinline__ unsigned smem_u32(const void* p) {
    return (unsigned)__cvta_generic_to_shared(p);
}

// ---------------------------------------------------------------------------
// Shared layout with bank-offset padding:
//   seq rows base = 0 mod 128, hA rows base = 64 mod 128, hB rows = 0 mod 128.
// So the two half-warp broadcast addresses of each LDS.128 hit disjoint banks
// (A pairs seq/hA: delta 64; B pairs hA/hB: delta 64) -> 1 wavefront per LDS.
// hA/hB rows padded to 64 floats (indices 40..63 stay zero; matching zero
// weights make the padded lanes free).
// ---------------------------------------------------------------------------
struct __align__(128) Smem {
    float seq[8][R][64];   // 8192 B, offset 0
    float pad1[16];        // 64 B
    float hA[R][64];       // offset 8256 (== 64 mod 128)
    float pad2[16];        // 64 B
    float hB[R][64];       // offset 9344 (== 0 mod 128)
    float zA[R][G4];
    float zB[R][G4];
    float t1[R][10], yy[R][10], cc[R][20], dd[R][10];
};

// ---------------------------------------------------------------------------
// Fused kernel: one block per 4 batch rows (grid 128 = single wave).
//   threads [0,320):   LSTM A.  warp w (0..9), gate g = w*16 + (lane&15),
//                      jh = lane>>4:  jh0 reduces x-part, jh1 reduces h-part.
//   threads [320,640): LSTM B, one step behind A, same split (hA vs hB part).
// Half-dot products combined with shfl_xor(16); each half-warp activates 2 of
// the 4 rows. Weight half-columns in registers as f32x2 pairs.
// ---------------------------------------------------------------------------
__global__ void __launch_bounds__(NT, 1)
fused_lstm_kernel(
    const float* __restrict__ seq,  const float* __restrict__ feat,
    const float* __restrict__ WaK,  const float* __restrict__ WaR, const float* __restrict__ ba,
    const float* __restrict__ WbK,  const float* __restrict__ WbR, const float* __restrict__ bb,
    const float* __restrict__ Wg,   const float* __restrict__ bg,
    const float* __restrict__ Wh,   const float* __restrict__ bh,
    const float* __restrict__ Wc,   const float* __restrict__ bc,
    const float* __restrict__ Wd,   const float* __restrict__ bd,
    const float* __restrict__ Wo,   const float* __restrict__ bo,
    float* __restrict__ out)
{
    __shared__ Smem s;

    const int tid  = threadIdx.x;
    const int b4   = blockIdx.x * R;
    const bool isA = tid < 320;
    const int gt   = isA ? tid : tid - 320;
    const int lane = gt & 31;
    const int g    = ((gt >> 5) << 4) | (lane & 15);   // gate column 0..159
    const int jh   = lane >> 4;                        // 0: x-part, 1: h-part
    const bool isTanhGate = (g >= 2 * HDIM && g < 3 * HDIM);

    // ---- per-thread half-column weights in registers (f32x2 pairs) ----
    ull w2[32];
    float bias;
    if (isA) {
        if (jh == 0) {           // x-part: all 64 inputs = 32 pairs
            #pragma unroll
            for (int p = 0; p < 32; p++)
                w2[p] = pack2(WaK[(2 * p) * G4 + g], WaK[(2 * p + 1) * G4 + g]);
        } else {                 // h-part: 40 real + 24 zero-padded
            #pragma unroll
            for (int p = 0; p < 20; p++)
                w2[p] = pack2(WaR[(2 * p) * G4 + g], WaR[(2 * p + 1) * G4 + g]);
            #pragma unroll
            for (int p = 20; p < 32; p++) w2[p] = 0ull;
        }
        bias = ba[g];
    } else {
        if (jh == 0) {           // x-part of B = hA (40 = 20 pairs)
            #pragma unroll
            for (int p = 0; p < 20; p++)
                w2[p] = pack2(WbK[(2 * p) * G4 + g], WbK[(2 * p + 1) * G4 + g]);
        } else {                 // h-part of B = hB
            #pragma unroll
            for (int p = 0; p < 20; p++)
                w2[p] = pack2(WbR[(2 * p) * G4 + g], WbR[(2 * p + 1) * G4 + g]);
        }
        #pragma unroll
        for (int p = 20; p < 32; p++) w2[p] = 0ull;
        bias = bb[g];
    }

    // ---- state-update (phase-2) thread mapping ----
    int r2 = 0, j2 = 0;
    if (tid < 160)                    { r2 = tid / HDIM;        j2 = tid % HDIM; }
    else if (tid >= 320 && tid < 480) { r2 = (tid - 320) / HDIM; j2 = (tid - 320) % HDIM; }
    float c_state = 0.0f;

    // ---- zero-init h states (incl. padding) ----
    if (tid < 256)                 ((float*)s.hA)[tid]       = 0.0f;
    else if (tid < 512)            ((float*)s.hB)[tid - 256] = 0.0f;

    // ---- cp.async prologue: steps 0..3 into ring slots 0..3 (4 groups) ----
    if (tid >= 480 && tid < 544) {
        const int k = tid - 480, row = k >> 4, ln = k & 15;
        const float* srcb = seq + ((size_t)(b4 + row) * T_STEPS) * F_IN + ln * 4;
        #pragma unroll
        for (int p = 0; p < 4; p++) {
            unsigned dst = smem_u32(&s.seq[p][row][ln * 4]);
            asm volatile("cp.async.ca.shared.global [%0], [%1], 16;\n\t"
                         "cp.async.commit_group;\n" :: "r"(dst), "l"(srcb + (size_t)p * F_IN));
        }
        asm volatile("cp.async.wait_group 3;");   // slot 0 ready
    }
    __syncthreads();

    // ---- main recurrence ----
    for (int t = 0; t <= T_STEPS; t++) {
        // prefetch step t+4 (empty commit group keeps wait accounting exact)
        if (tid >= 480 && tid < 544) {
            const int k = tid - 480, row = k >> 4, ln = k & 15;
            const int tf = t + 4;
            if (tf < T_STEPS) {
                unsigned dst = smem_u32(&s.seq[tf & 7][row][ln * 4]);
                const float* src = seq + ((size_t)(b4 + row) * T_STEPS + tf) * F_IN + ln * 4;
                asm volatile("cp.async.ca.shared.global [%0], [%1], 16;" :: "r"(dst), "l"(src));
            }
            asm volatile("cp.async.commit_group;");
        }

        // ---- phase 1: half-dot products, shfl combine, activate ----
        if (isA) {
            if (t < T_STEPS) {
                const ulonglong2* base = (jh == 0)
                    ? (const ulonglong2*)&s.seq[t & 7][0][0]
                    : (const ulonglong2*)&s.hA[0][0];
                float tot[R];
                #pragma unroll
                for (int pr = 0; pr < 2; pr++) {        // row pairs (0,1) (2,3)
                    const ulonglong2* p0 = base + (2 * pr) * 16;
                    const ulonglong2* p1 = p0 + 16;
                    ull a = 0ull, b = 0ull;
                    #pragma unroll
                    for (int q = 0; q < 16; q++) {
                        ulonglong2 v0 = p0[q], v1 = p1[q];
                        ffma2(a, w2[2 * q],     v0.x);
                        ffma2(a, w2[2 * q + 1], v0.y);
                        ffma2(b, w2[2 * q],     v1.x);
                        ffma2(b, w2[2 * q + 1], v1.y);
                    }
                    float x0, x1;
                    unpack2(a, x0, x1); tot[2 * pr]     = x0 + x1;
                    unpack2(b, x0, x1); tot[2 * pr + 1] = x0 + x1;
                }
                #pragma unroll
                for (int r = 0; r < R; r++)
                    tot[r] += __shfl_xor_sync(0xffffffffu, tot[r], 16);
                const int rb = jh * 2;                  // jh0 -> rows 0,1; jh1 -> 2,3
                #pragma unroll
                for (int k = 0; k < 2; k++) {
                    const int r = rb + k;
                    float z = bias + tot[r];
                    s.zA[r][g] = isTanhGate ? tanh_f(z) : sigmoid_f(z);
                }
            }
        } else {
            if (t >= 1) {
                const ulonglong2* base = (jh == 0)
                    ? (const ulonglong2*)&s.hA[0][0]    // B's input = hA_{t-1}
                    : (const ulonglong2*)&s.hB[0][0];   // recurrent hB
                float tot[R];
                #pragma unroll
                for (int pr = 0; pr < 2; pr++) {
                    const ulonglong2* p0 = base + (2 * pr) * 16;
                    const ulonglong2* p1 = p0 + 16;
                    ull a = 0ull, b = 0ull;
                    #pragma unroll
                    for (int q = 0; q < 10; q++) {      // 40 real values = 10 u2
                        ulonglong2 v0 = p0[q], v1 = p1[q];
                        ffma2(a, w2[2 * q],     v0.x);
                        ffma2(a, w2[2 * q + 1], v0.y);
                        ffma2(b, w2[2 * q],     v1.x);
                        ffma2(b, w2[2 * q + 1], v1.y);
                    }
                    float x0, x1;
                    unpack2(a, x0, x1); tot[2 * pr]     = x0 + x1;
                    unpack2(b, x0, x1); tot[2 * pr + 1] = x0 + x1;
                }
                #pragma unroll
                for (int r = 0; r < R; r++)
                    tot[r] += __shfl_xor_sync(0xffffffffu, tot[r], 16);
                const int rb = jh * 2;
                #pragma unroll
                for (int k = 0; k < 2; k++) {
                    const int r = rb + k;
                    float z = bias + tot[r];
                    s.zB[r][g] = isTanhGate ? tanh_f(z) : sigmoid_f(z);
                }
            }
        }
        __syncthreads();

        // ---- phase 2: cell/state update, one (row, j) per thread ----
        if (tid < 160) {
            if (t < T_STEPS) {
                float zi = s.zA[r2][j2],           zf = s.zA[r2][j2 + 40],
                      zg = s.zA[r2][j2 + 80],      zo = s.zA[r2][j2 + 120];
                c_state = zf * c_state + zi * zg;
                s.hA[r2][j2] = zo * tanh_f(c_state);
            }
        } else if (tid >= 320 && tid < 480) {
            if (t >= 1) {
                float zi = s.zB[r2][j2],           zf = s.zB[r2][j2 + 40],
                      zg = s.zB[r2][j2 + 80],      zo = s.zB[r2][j2 + 120];
                c_state = zf * c_state + zi * zg;
                s.hB[r2][j2] = zo * tanh_f(c_state);
            }
        } else if (tid >= 480 && tid < 544) {
            asm volatile("cp.async.wait_group 3;");   // slot t+1 ready
        }
        __syncthreads();
    }

    // ---- dense tail: threads [0,160) = (r, u) ----
    {
        const int r = r2, u = j2;
        const bool act = tid < 160;
        const float* fb = feat + (size_t)(b4 + r) * F_IN;
        if (act && u < 10) {
            float a = bg[u];
            #pragma unroll 8
            for (int j = 0; j < F_IN; j++) a = fmaf(fb[j], Wg[j * 10 + u], a);
            s.t1[r][u] = tanh_f(a);
        }
        __syncthreads();
        if (act && u < 10) {
            float a = bh[u];
            #pragma unroll
            for (int j = 0; j < 10; j++) a = fmaf(s.t1[r][j], Wh[j * 10 + u], a);
            s.yy[r][u] = tanh_f(a);
        }
        __syncthreads();
        if (act && u < 20) {
            float a = bc[u];
            #pragma unroll
            for (int j = 0; j < HDIM; j++) a = fmaf(s.hB[r][j], Wc[j * 20 + u], a);
            #pragma unroll
            for (int j = 0; j < 10; j++)   a = fmaf(s.yy[r][j], Wc[(HDIM + j) * 20 + u], a);
            s.cc[r][u] = fmaxf(a, 0.0f);
        }
        __syncthreads();
        if (act && u < 10) {
            float a = bd[u];
            #pragma unroll
            for (int j = 0; j < 20; j++) a = fmaf(s.cc[r][j], Wd[j * 10 + u], a);
            s.dd[r][u] = fmaxf(a, 0.0f);
        }
        __syncthreads();
        if (act && u == 0) {
            float a = bo[0];
            #pragma unroll
            for (int j = 0; j < 10; j++) a = fmaf(s.dd[r][j], Wo[j], a);
            out[b4 + r] = sigmoid_f(a);
        }
    }
}

// ---------------------------------------------------------------------------
extern "C" void kernel_launch(void* const* d_in, const int* in_sizes, int n_in,
                              void* d_out, int out_size)
{
    (void)in_sizes; (void)n_in; (void)out_size;
    const float* seq  = (const float*)d_in[0];
    const float* feat = (const float*)d_in[1];
    const float* WaK  = (const float*)d_in[2];
    const float* WaR  = (const float*)d_in[3];
    const float* ba   = (const float*)d_in[4];
    const float* WbK  = (const float*)d_in[5];
    const float* WbR  = (const float*)d_in[6];
    const float* bb   = (const float*)d_in[7];
    const float* Wg   = (const float*)d_in[8];
    const float* bg   = (const float*)d_in[9];
    const float* Wh   = (const float*)d_in[10];
    const float* bh   = (const float*)d_in[11];
    const float* Wc   = (const float*)d_in[12];
    const float* bc   = (const float*)d_in[13];
    const float* Wd   = (const float*)d_in[14];
    const float* bd   = (const float*)d_in[15];
    const float* Wo   = (const float*)d_in[16];
    const float* bo   = (const float*)d_in[17];
    float* out = (float*)d_out;

    fused_lstm_kernel<<<512 / R, NT>>>(seq, feat, WaK, WaR, ba, WbK, WbR, bb,
                                       Wg, bg, Wh, bh, Wc, bc, Wd, bd, Wo, bo, out);
}

// round 5
// speedup vs baseline: 1.3127x; 1.3127x over previous
#include <cuda_runtime.h>
#include <cstdint>

#define T_STEPS 1024
#define F_IN    64
#define HDIM    40
#define G4      160   // 4*H
#define R       4     // batch rows per block
#define NT      320   // 10 warps: 5 LSTM-A, 5 LSTM-B

typedef unsigned long long ull;

// ---------------------------------------------------------------------------
// Packed f32x2 helpers
// ---------------------------------------------------------------------------
__device__ __forceinline__ ull pack2(float a, float b) {
    ull r; asm("mov.b64 %0, {%1,%2};" : "=l"(r) : "f"(a), "f"(b)); return r;
}
__device__ __forceinline__ void unpack2(ull v, float& a, float& b) {
    asm("mov.b64 {%0,%1}, %2;" : "=f"(a), "=f"(b) : "l"(v));
}
__device__ __forceinline__ void ffma2(ull& d, ull a, ull b) {
    asm("fma.rn.f32x2 %0, %1, %2, %0;" : "+l"(d) : "l"(a), "l"(b));
}

// ---------------------------------------------------------------------------
// MUFU activations
// ---------------------------------------------------------------------------
__device__ __forceinline__ float sigmoid_f(float x) {
    float e, r;
    asm("ex2.approx.f32 %0, %1;" : "=f"(e) : "f"(-1.4426950408889634f * x));
    asm("rcp.approx.f32 %0, %1;" : "=f"(r) : "f"(1.0f + e));
    return r;
}
__device__ __forceinline__ float tanh_f(float x) {
    float e, r;
    asm("ex2.approx.f32 %0, %1;" : "=f"(e) : "f"(2.8853900817779268f * x));
    asm("rcp.approx.f32 %0, %1;" : "=f"(r) : "f"(1.0f + e));
    return 1.0f - 2.0f * r;
}
// branchless gate activation: v = aa * sigmoid-core(mm*z) + bb
__device__ __forceinline__ float gate_act(float z, float mm, float aa, float bb) {
    float e, r;
    asm("ex2.approx.f32 %0, %1;" : "=f"(e) : "f"(mm * z));
    asm("rcp.approx.f32 %0, %1;" : "=f"(r) : "f"(1.0f + e));
    return fmaf(aa, r, bb);
}

__device__ __forceinline__ unsigned smem_u32(const void* p) {
    return (unsigned)__cvta_generic_to_shared(p);
}

struct __align__(16) Smem {
    float seq[8][R][F_IN];      // cp.async ring (8 KB)
    float hA[R][HDIM];          // rows are 160B -> 16B aligned
    float hB[R][HDIM];
    float t1[R][10], yy[R][10], cc[R][20], dd[R][10];
};

// ---------------------------------------------------------------------------
// Lane layout (per LSTM): warp w in [0,5), lane = q*8 + u
//   q = gate (0:i 1:f 2:g 3:o), u in [0,8), unit j = w*8+u, column g = q*40+j.
// After activation, shfl_xor 8/16/24 gathers f,g,o into the q==0 lane, which
// owns c_state for unit j (4 rows) and writes h. ONE barrier per step.
// A's x-dot (64-long) is computed one step ahead (xacc), off the h-chain.
// ---------------------------------------------------------------------------
__global__ void __launch_bounds__(NT, 1)
fused_lstm_kernel(
    const float* __restrict__ seq,  const float* __restrict__ feat,
    const float* __restrict__ WaK,  const float* __restrict__ WaR, const float* __restrict__ ba,
    const float* __restrict__ WbK,  const float* __restrict__ WbR, const float* __restrict__ bb,
    const float* __restrict__ Wg,   const float* __restrict__ bg,
    const float* __restrict__ Wh,   const float* __restrict__ bh,
    const float* __restrict__ Wc,   const float* __restrict__ bc,
    const float* __restrict__ Wd,   const float* __restrict__ bd,
    const float* __restrict__ Wo,   const float* __restrict__ bo,
    float* __restrict__ out)
{
    __shared__ Smem s;

    const int tid  = threadIdx.x;
    const int b4   = blockIdx.x * R;
    const bool isA = tid < 160;
    const int gt   = isA ? tid : tid - 160;
    const int w    = gt >> 5;          // warp within its LSTM, 0..4
    const int lane = gt & 31;
    const int q    = lane >> 3;        // gate index
    const int u    = lane & 7;
    const int j    = w * 8 + u;        // hidden unit 0..39
    const int g    = q * HDIM + j;     // gate column 0..159

    // activation constants (q==2 -> tanh = 2*sig(2x)-1)
    const bool isG = (q == 2);
    const float mm = isG ? -2.8853900817779268f : -1.4426950408889634f;
    const float aa = isG ? 2.0f : 1.0f;
    const float bbv = isG ? -1.0f : 0.0f;

    // ---- per-thread full weight column, f32x2 packed ----
    ull wk2[32];   // A: 32 pairs (x, 64). B: 20 pairs (hA input, 40).
    ull wr2[20];   // recurrent (40)
    float bias;
    if (isA) {
        #pragma unroll
        for (int p = 0; p < 32; p++)
            wk2[p] = pack2(WaK[(2 * p) * G4 + g], WaK[(2 * p + 1) * G4 + g]);
        #pragma unroll
        for (int p = 0; p < 20; p++)
            wr2[p] = pack2(WaR[(2 * p) * G4 + g], WaR[(2 * p + 1) * G4 + g]);
        bias = ba[g];
    } else {
        #pragma unroll
        for (int p = 0; p < 20; p++)
            wk2[p] = pack2(WbK[(2 * p) * G4 + g], WbK[(2 * p + 1) * G4 + g]);
        #pragma unroll
        for (int p = 12; p < 32; p++) wk2[p] = 0ull;   // unused tail
        #pragma unroll
        for (int p = 0; p < 20; p++)
            wr2[p] = pack2(WbR[(2 * p) * G4 + g], WbR[(2 * p + 1) * G4 + g]);
        bias = bb[g];
    }

    float c_state[R] = {0.f, 0.f, 0.f, 0.f};   // live in q==0 lanes
    float xacc[R]    = {0.f, 0.f, 0.f, 0.f};   // A only: x-dot for step t

    // ---- zero h states ----
    if (tid < R * HDIM)       ((float*)s.hA)[tid]        = 0.0f;
    else if (tid < 2*R*HDIM)  ((float*)s.hB)[tid - 160]  = 0.0f;

    // ---- cp.async prologue: slots 0..3 (4 groups), ensure slots 0,1 done ----
    if (tid >= 160 && tid < 224) {
        const int k = tid - 160, row = k >> 4, ln = k & 15;
        const float* srcb = seq + ((size_t)(b4 + row) * T_STEPS) * F_IN + ln * 4;
        #pragma unroll
        for (int p = 0; p < 4; p++) {
            unsigned dst = smem_u32(&s.seq[p][row][ln * 4]);
            asm volatile("cp.async.ca.shared.global [%0], [%1], 16;\n\t"
                         "cp.async.commit_group;\n" :: "r"(dst), "l"(srcb + (size_t)p * F_IN));
        }
        asm volatile("cp.async.wait_group 2;");   // slots 0,1 complete
    }
    __syncthreads();

    // ---- A: xacc for step 0 from slot 0 ----
    if (isA) {
        #pragma unroll
        for (int r = 0; r < R; r++) {
            const ulonglong2* x2 = (const ulonglong2*)&s.seq[0][r][0];
            ull a0 = 0ull, a1 = 0ull;
            #pragma unroll
            for (int p = 0; p < 16; p++) {
                ulonglong2 v = x2[p];
                ffma2(a0, wk2[2 * p],     v.x);
                ffma2(a1, wk2[2 * p + 1], v.y);
            }
            float x0, x1, x2f, x3;
            unpack2(a0, x0, x1); unpack2(a1, x2f, x3);
            xacc[r] = (x0 + x2f) + (x1 + x3);
        }
    }

    // ---- main recurrence: ONE barrier per step ----
    for (int t = 0; t <= T_STEPS; t++) {
        // loaders: issue prefetch for slot t+4 early (fills latency)
        if (tid >= 160 && tid < 224) {
            const int k = tid - 160, row = k >> 4, ln = k & 15;
            const int tf = t + 4;
            if (tf < T_STEPS) {
                unsigned dst = smem_u32(&s.seq[tf & 7][row][ln * 4]);
                const float* src = seq + ((size_t)(b4 + row) * T_STEPS + tf) * F_IN + ln * 4;
                asm volatile("cp.async.ca.shared.global [%0], [%1], 16;" :: "r"(dst), "l"(src));
            }
            asm volatile("cp.async.commit_group;");
        }

        if (isA) {
            if (t < T_STEPS) {
                // critical path: 40-long h-dot only
                float v[R];
                #pragma unroll
                for (int r = 0; r < R; r++) {
                    const ulonglong2* h2 = (const ulonglong2*)&s.hA[r][0];
                    ull a0 = 0ull, a1 = 0ull;
                    #pragma unroll
                    for (int p = 0; p < 10; p++) {
                        ulonglong2 hv = h2[p];
                        ffma2(a0, wr2[2 * p],     hv.x);
                        ffma2(a1, wr2[2 * p + 1], hv.y);
                    }
                    float x0, x1, x2f, x3;
                    unpack2(a0, x0, x1); unpack2(a1, x2f, x3);
                    float z = bias + xacc[r] + ((x0 + x2f) + (x1 + x3));
                    v[r] = gate_act(z, mm, aa, bbv);
                }
                // warp exchange + state update (q==0 lanes own unit j)
                #pragma unroll
                for (int r = 0; r < R; r++) {
                    float fv = __shfl_xor_sync(0xffffffffu, v[r], 8);
                    float gv = __shfl_xor_sync(0xffffffffu, v[r], 16);
                    float ov = __shfl_xor_sync(0xffffffffu, v[r], 24);
                    if (q == 0) {
                        c_state[r] = fmaf(fv, c_state[r], v[r] * gv);
                        s.hA[r][j] = ov * tanh_f(c_state[r]);
                    }
                }
            }
            // off-path: x-dot for step t+1 from prefetched slot
            if (t + 1 < T_STEPS) {
                #pragma unroll
                for (int r = 0; r < R; r++) {
                    const ulonglong2* x2 = (const ulonglong2*)&s.seq[(t + 1) & 7][r][0];
                    ull a0 = 0ull, a1 = 0ull;
                    #pragma unroll
                    for (int p = 0; p < 16; p++) {
                        ulonglong2 xv = x2[p];
                        ffma2(a0, wk2[2 * p],     xv.x);
                        ffma2(a1, wk2[2 * p + 1], xv.y);
                    }
                    float x0, x1, x2f, x3;
                    unpack2(a0, x0, x1); unpack2(a1, x2f, x3);
                    xacc[r] = (x0 + x2f) + (x1 + x3);
                }
            }
        } else {
            if (t >= 1) {
                float v[R];
                #pragma unroll
                for (int r = 0; r < R; r++) {
                    const ulonglong2* xa = (const ulonglong2*)&s.hA[r][0];  // input = hA_{t-1}
                    const ulonglong2* hb = (const ulonglong2*)&s.hB[r][0];  // recurrent
                    ull a0 = 0ull, a1 = 0ull;
                    #pragma unroll
                    for (int p = 0; p < 10; p++) {
                        ulonglong2 xv = xa[p];
                        ulonglong2 hv = hb[p];
                        ffma2(a0, wk2[2 * p],     xv.x);
                        ffma2(a1, wk2[2 * p + 1], xv.y);
                        ffma2(a0, wr2[2 * p],     hv.x);
                        ffma2(a1, wr2[2 * p + 1], hv.y);
                    }
                    float x0, x1, x2f, x3;
                    unpack2(a0, x0, x1); unpack2(a1, x2f, x3);
                    float z = bias + ((x0 + x2f) + (x1 + x3));
                    v[r] = gate_act(z, mm, aa, bbv);
                }
                #pragma unroll
                for (int r = 0; r < R; r++) {
                    float fv = __shfl_xor_sync(0xffffffffu, v[r], 8);
                    float gv = __shfl_xor_sync(0xffffffffu, v[r], 16);
                    float ov = __shfl_xor_sync(0xffffffffu, v[r], 24);
                    if (q == 0) {
                        c_state[r] = fmaf(fv, c_state[r], v[r] * gv);
                        s.hB[r][j] = ov * tanh_f(c_state[r]);
                    }
                }
            }
            if (tid >= 160 && tid < 224)
                asm volatile("cp.async.wait_group 2;");   // slot t+2 complete
        }
        __syncthreads();
    }

    // ---- dense tail: threads [0,160) = (r, u') ----
    {
        const int r = tid / HDIM;      // valid for tid<160
        const int uu = tid % HDIM;
        const bool act = tid < 160;
        const float* fb = feat + (size_t)(b4 + r) * F_IN;
        if (act && uu < 10) {
            float a = bg[uu];
            #pragma unroll 8
            for (int k = 0; k < F_IN; k++) a = fmaf(fb[k], Wg[k * 10 + uu], a);
            s.t1[r][uu] = tanh_f(a);
        }
        __syncthreads();
        if (act && uu < 10) {
            float a = bh[uu];
            #pragma unroll
            for (int k = 0; k < 10; k++) a = fmaf(s.t1[r][k], Wh[k * 10 + uu], a);
            s.yy[r][uu] = tanh_f(a);
        }
        __syncthreads();
        if (act && uu < 20) {
            float a = bc[uu];
            #pragma unroll
            for (int k = 0; k < HDIM; k++) a = fmaf(s.hB[r][k], Wc[k * 20 + uu], a);
            #pragma unroll
            for (int k = 0; k < 10; k++)   a = fmaf(s.yy[r][k], Wc[(HDIM + k) * 20 + uu], a);
            s.cc[r][uu] = fmaxf(a, 0.0f);
        }
        __syncthreads();
        if (act && uu < 10) {
            float a = bd[uu];
            #pragma unroll
            for (int k = 0; k < 20; k++) a = fmaf(s.cc[r][k], Wd[k * 10 + uu], a);
            s.dd[r][uu] = fmaxf(a, 0.0f);
        }
        __syncthreads();
        if (act && uu == 0) {
            float a = bo[0];
            #pragma unroll
            for (int k = 0; k < 10; k++) a = fmaf(s.dd[r][k], Wo[k], a);
            out[b4 + r] = sigmoid_f(a);
        }
    }
}

// ---------------------------------------------------------------------------
extern "C" void kernel_launch(void* const* d_in, const int* in_sizes, int n_in,
                              void* d_out, int out_size)
{
    (void)in_sizes; (void)n_in; (void)out_size;
    const float* seq  = (const float*)d_in[0];
    const float* feat = (const float*)d_in[1];
    const float* WaK  = (const float*)d_in[2];
    const float* WaR  = (const float*)d_in[3];
    const float* ba   = (const float*)d_in[4];
    const float* WbK  = (const float*)d_in[5];
    const float* WbR  = (const float*)d_in[6];
    const float* bb   = (const float*)d_in[7];
    const float* Wg   = (const float*)d_in[8];
    const float* bg   = (const float*)d_in[9];
    const float* Wh   = (const float*)d_in[10];
    const float* bh   = (const float*)d_in[11];
    const float* Wc   = (const float*)d_in[12];
    const float* bc   = (const float*)d_in[13];
    const float* Wd   = (const float*)d_in[14];
    const float* bd   = (const float*)d_in[15];
    const float* Wo   = (const float*)d_in[16];
    const float* bo   = (const float*)d_in[17];
    float* out = (float*)d_out;

    fused_lstm_kernel<<<512 / R, NT>>>(seq, feat, WaK, WaR, ba, WbK, WbR, bb,
                                       Wg, bg, Wh, bh, Wc, bc, Wd, bd, Wo, bo, out);
}